// round 16
// baseline (speedup 1.0000x reference)
#include <cuda_runtime.h>
#include <math_constants.h>

#define NN   100000
#define EE   800000
#define FIN  14
#define HC   128      // H1*C1
#define H1   4
#define C1   32
#define C2   21
#define SLOPE 0.2f
#define MAXDEG 64     // Poisson(8) max over 100k nodes ~ 30; 64 = huge margin

// ---- scratch (device globals; no allocation allowed) ----
__device__ __align__(16) float g_xl1[NN * HC];
__device__ __align__(16) float g_xr1[NN * HC];
__device__ __align__(16) float g_h  [NN * HC];
__device__ float g_hl2[NN * C2 + 32];
__device__ float g_hr2[NN * C2 + 32];
__device__ int   g_cnt[NN];
__device__ int   g_adj[NN * MAXDEG];   // padded adjacency; slot cnt holds the self loop

// ---------------- adjacency build ----------------
__global__ void k_zero_cnt() {
    int i = blockIdx.x * blockDim.x + threadIdx.x;
    if (i < NN) g_cnt[i] = 0;
}

__global__ void k_bucket(const int* __restrict__ src, const int* __restrict__ dst) {
    int e = blockIdx.x * blockDim.x + threadIdx.x;
    if (e < EE) {
        int d = dst[e];
        int slot = atomicAdd(&g_cnt[d], 1);
        if (slot < MAXDEG - 1) g_adj[(d << 6) + slot] = src[e];   // keep last slot for self
    }
}

// write self-loop into slot cnt; clamp cnt once so agg kernels are predicate-free
__global__ void k_selfslot() {
    int i = blockIdx.x * blockDim.x + threadIdx.x;
    if (i < NN) {
        int c = g_cnt[i];
        if (c > MAXDEG - 1) { c = MAXDEG - 1; g_cnt[i] = c; }
        g_adj[(i << 6) + c] = i;
    }
}

// ---------------- Layer 1 GEMM: 256 threads, 256-node tile, 2 cols/thread ----------------
#define G1_TN 256
#define G1_STRIDE 260
__global__ void k_gemm1(const float* __restrict__ x,
                        const float* __restrict__ Wl, const float* __restrict__ bl,
                        const float* __restrict__ Wr, const float* __restrict__ br) {
    __shared__ float sxT[FIN * G1_STRIDE];
    int t = threadIdx.x;              // 256 threads
    int base = blockIdx.x * G1_TN;
    int nh   = t >> 7;                // node half
    int half = (t & 127) >> 6;        // 0 = l, 1 = r
    int c2   = (t & 63) * 2;
    const float* W = half ? Wr : Wl;
    const float* B = half ? br : bl;
    float w0[FIN], w1[FIN];
#pragma unroll
    for (int k = 0; k < FIN; k++) {
        w0[k] = __ldg(&W[k * HC + c2]);
        w1[k] = __ldg(&W[k * HC + c2 + 1]);
    }
    float b0 = __ldg(&B[c2]), b1 = __ldg(&B[c2 + 1]);

    for (int idx = t; idx < G1_TN * FIN; idx += 256) {
        int n = idx / FIN, k = idx - n * FIN;
        float v = (base + n < NN) ? x[(base + n) * FIN + k] : 0.f;
        sxT[k * G1_STRIDE + n] = v;
    }
    __syncthreads();

    float* outp = half ? g_xr1 : g_xl1;
    int noff = nh * 128;
#pragma unroll 2
    for (int n0 = 0; n0 < 128; n0 += 4) {
        float a00 = b0, a01 = b0, a02 = b0, a03 = b0;
        float a10 = b1, a11 = b1, a12 = b1, a13 = b1;
#pragma unroll
        for (int k = 0; k < FIN; k++) {
            float4 xv = *(const float4*)&sxT[k * G1_STRIDE + noff + n0];
            a00 += xv.x * w0[k]; a10 += xv.x * w1[k];
            a01 += xv.y * w0[k]; a11 += xv.y * w1[k];
            a02 += xv.z * w0[k]; a12 += xv.z * w1[k];
            a03 += xv.w * w0[k]; a13 += xv.w * w1[k];
        }
        int n = base + noff + n0;
        if (n + 3 < NN) {
            *(float2*)&outp[(n + 0) * HC + c2] = make_float2(a00, a10);
            *(float2*)&outp[(n + 1) * HC + c2] = make_float2(a01, a11);
            *(float2*)&outp[(n + 2) * HC + c2] = make_float2(a02, a12);
            *(float2*)&outp[(n + 3) * HC + c2] = make_float2(a03, a13);
        } else {
            if (n + 0 < NN) *(float2*)&outp[(n + 0) * HC + c2] = make_float2(a00, a10);
            if (n + 1 < NN) *(float2*)&outp[(n + 1) * HC + c2] = make_float2(a01, a11);
            if (n + 2 < NN) *(float2*)&outp[(n + 2) * HC + c2] = make_float2(a02, a12);
            if (n + 3 < NN) *(float2*)&outp[(n + 3) * HC + c2] = make_float2(a03, a13);
        }
    }
}

// ---------------- Layer 1 aggregation: champion loop + instruction diet ----------------
__global__ void k_agg1(const float* __restrict__ att1, const float* __restrict__ bias1) {
    int tid = threadIdx.x, wid = tid >> 5, lane = tid & 31;
    int node = blockIdx.x * 8 + wid;
    if (node >= NN) return;
    int c0 = lane * 4;
    float4 xr4 = *(const float4*)&g_xr1[node * HC + c0];
    float att[4];
#pragma unroll
    for (int j = 0; j < 4; j++) att[j] = att1[(lane >> 3) * C1 + (c0 & 31) + j];
    int adj0 = node << 6;
    int cnt  = g_cnt[node];                      // pre-clamped by k_selfslot
    int total = cnt + 1;                         // slot cnt = self loop (real slot now)

    // predicate-free: min(i,cnt) clamps any overrun to the self slot
    auto srcof = [&](int i) -> int {
        return __ldg(&g_adj[adj0 + min(i, cnt)]);
    };
    auto rowof = [&](int i) -> float4 {
        return *(const float4*)&g_xl1[srcof(i) * HC + c0];
    };
    auto score = [&](const float4& v) -> float {
        // leaky(v) = max(v, SLOPE*v) for SLOPE<1 : FMUL+FMNMX instead of FSETP+FMUL+SEL
        float t0 = v.x + xr4.x; float a0 = fmaxf(t0, SLOPE * t0);
        float t1 = v.y + xr4.y; float a1 = fmaxf(t1, SLOPE * t1);
        float t2 = v.z + xr4.z; float a2 = fmaxf(t2, SLOPE * t2);
        float t3 = v.w + xr4.w; float a3 = fmaxf(t3, SLOPE * t3);
        float p = a0 * att[0] + a1 * att[1] + a2 * att[2] + a3 * att[3];
        p += __shfl_xor_sync(0xffffffffu, p, 1);
        p += __shfl_xor_sync(0xffffffffu, p, 2);
        p += __shfl_xor_sync(0xffffffffu, p, 4);
        return p;
    };

    float dsum0 = 0.f, dsum1 = 0.f;
    float4 acc0 = make_float4(0.f, 0.f, 0.f, 0.f);
    float4 acc1 = make_float4(0.f, 0.f, 0.f, 0.f);

    float4 vA = rowof(0);
    float4 vB = rowof(1);
    int e = 0;
    for (; e + 1 < total; e += 2) {
        float4 vA2 = rowof(e + 2);               // overrun clamps to self slot
        float4 vB2 = rowof(e + 3);
        float pA = score(vA);                    // two independent shuffle chains
        float pB = score(vB);
        float wA = __expf(pA);
        float wB = __expf(pB);
        dsum0 += wA;
        acc0.x += wA * vA.x; acc0.y += wA * vA.y; acc0.z += wA * vA.z; acc0.w += wA * vA.w;
        dsum1 += wB;
        acc1.x += wB * vB.x; acc1.y += wB * vB.y; acc1.z += wB * vB.z; acc1.w += wB * vB.w;
        vA = vA2; vB = vB2;
    }
    if (e < total) {                             // odd tail
        float pA = score(vA);
        float wA = __expf(pA);
        dsum0 += wA;
        acc0.x += wA * vA.x; acc0.y += wA * vA.y; acc0.z += wA * vA.z; acc0.w += wA * vA.w;
    }
    float inv = 1.f / (dsum0 + dsum1);
    float o0 = (acc0.x + acc1.x) * inv + bias1[c0];
    float o1 = (acc0.y + acc1.y) * inv + bias1[c0 + 1];
    float o2 = (acc0.z + acc1.z) * inv + bias1[c0 + 2];
    float o3 = (acc0.w + acc1.w) * inv + bias1[c0 + 3];
    o0 = o0 > 0.f ? o0 : (__expf(o0) - 1.f);     // ELU
    o1 = o1 > 0.f ? o1 : (__expf(o1) - 1.f);
    o2 = o2 > 0.f ? o2 : (__expf(o2) - 1.f);
    o3 = o3 > 0.f ? o3 : (__expf(o3) - 1.f);
    *(float4*)&g_h[node * HC + c0] = make_float4(o0, o1, o2, o3);
}

// ---------------- Layer 2 GEMM: 128-node tile, 128 threads ----------------
#define G2_TM 128
__global__ void k_gemm2(const float* __restrict__ Wl, const float* __restrict__ bl,
                        const float* __restrict__ Wr, const float* __restrict__ br) {
    __shared__ float sh[64][G2_TM + 1];
    __shared__ float sw[64][48];
    int tid = threadIdx.x;                // 128 threads
    int base = blockIdx.x * G2_TM;
    int node = base + tid;
    float acc[44];
#pragma unroll
    for (int j = 0; j < 44; j++) acc[j] = 0.f;

    for (int half = 0; half < 2; half++) {
        int k0 = half * 64;
        for (int idx = tid; idx < 64 * 21; idx += 128) {
            int kk = idx / 21, j = idx % 21;
            sw[kk][j]      = Wl[(k0 + kk) * C2 + j];
            sw[kk][21 + j] = Wr[(k0 + kk) * C2 + j];
        }
        for (int idx = tid; idx < 64; idx += 128) {
#pragma unroll
            for (int j = 42; j < 48; j++) sw[idx][j] = 0.f;
        }
        for (int idx = tid; idx < 32 * G2_TM; idx += 128) {
            int m = idx >> 5, kp = idx & 31;
            float2 hv = make_float2(0.f, 0.f);
            if (base + m < NN) hv = *(const float2*)&g_h[(base + m) * HC + k0 + kp * 2];
            sh[kp * 2 + 0][m] = hv.x;
            sh[kp * 2 + 1][m] = hv.y;
        }
        __syncthreads();
#pragma unroll 4
        for (int k = 0; k < 64; k++) {
            float hk = sh[k][tid];
#pragma unroll
            for (int j4 = 0; j4 < 44; j4 += 4) {
                float4 w4 = *(const float4*)&sw[k][j4];
                acc[j4]     += hk * w4.x;
                acc[j4 + 1] += hk * w4.y;
                acc[j4 + 2] += hk * w4.z;
                acc[j4 + 3] += hk * w4.w;
            }
        }
        __syncthreads();
    }
    if (node < NN) {
#pragma unroll
        for (int j = 0; j < C2; j++) g_hl2[node * C2 + j] = acc[j] + bl[j];
#pragma unroll
        for (int j = 0; j < C2; j++) g_hr2[node * C2 + j] = acc[21 + j] + br[j];
    }
}

// ---------------- Layer 2 aggregation: champion loop + instruction diet ----------------
__global__ void k_agg2(const float* __restrict__ att2, const float* __restrict__ bias2,
                       float* __restrict__ out) {
    int tid = threadIdx.x, wid = tid >> 5, lane = tid & 31;
    int node = blockIdx.x * 8 + wid;
    if (node >= NN) return;
    bool act = lane < C2;
    float xr = act ? g_hr2[node * C2 + lane] : 0.f;
    float av = act ? att2[lane] : 0.f;
    int adj0 = node << 6;
    int cnt  = g_cnt[node];
    int total = cnt + 1;

    auto srcof = [&](int i) -> int {
        return __ldg(&g_adj[adj0 + min(i, cnt)]);
    };
    auto loadx = [&](int i) -> float {
        int s = srcof(i);
        return act ? __ldg(&g_hl2[s * C2 + lane]) : 0.f;
    };
    auto score = [&](float xs) -> float {
        float t = xs + xr;
        float vv = fmaxf(t, SLOPE * t);           // leaky via fmax
        float p = vv * av;                        // inactive lanes contribute 0
#pragma unroll
        for (int off = 16; off; off >>= 1) p += __shfl_xor_sync(0xffffffffu, p, off);
        return p;
    };

    float dsum0 = 0.f, dsum1 = 0.f, acc0 = 0.f, acc1 = 0.f;
    float xA = loadx(0);
    float xB = loadx(1);
    int e = 0;
    for (; e + 1 < total; e += 2) {
        float xA2 = loadx(e + 2);
        float xB2 = loadx(e + 3);
        float pA = score(xA);
        float pB = score(xB);
        float wA = __expf(pA);
        float wB = __expf(pB);
        dsum0 += wA; acc0 += wA * xA;
        dsum1 += wB; acc1 += wB * xB;
        xA = xA2; xB = xB2;
    }
    if (e < total) {
        float pA = score(xA);
        float wA = __expf(pA);
        dsum0 += wA; acc0 += wA * xA;
    }
    if (act) out[node * C2 + lane] = (acc0 + acc1) / (dsum0 + dsum1) + bias2[lane];
}

// ---------------- launch ----------------
extern "C" void kernel_launch(void* const* d_in, const int* in_sizes, int n_in,
                              void* d_out, int out_size) {
    const float* x     = (const float*)d_in[0];
    const int*   ei    = (const int*)  d_in[1];
    const float* W1l   = (const float*)d_in[2];
    const float* b1l   = (const float*)d_in[3];
    const float* W1r   = (const float*)d_in[4];
    const float* b1r   = (const float*)d_in[5];
    const float* att1  = (const float*)d_in[6];
    const float* bias1 = (const float*)d_in[7];
    const float* W2l   = (const float*)d_in[8];
    const float* b2l   = (const float*)d_in[9];
    const float* W2r   = (const float*)d_in[10];
    const float* b2r   = (const float*)d_in[11];
    const float* att2  = (const float*)d_in[12];
    const float* bias2 = (const float*)d_in[13];
    const int* src = ei;         // edge_index[0]
    const int* dst = ei + EE;    // edge_index[1]

    // Fork: gemm1 runs concurrently with the adjacency build.
    cudaStream_t s2;
    cudaEvent_t evFork, evJoin;
    cudaStreamCreateWithFlags(&s2, cudaStreamNonBlocking);
    cudaEventCreateWithFlags(&evFork, cudaEventDisableTiming);
    cudaEventCreateWithFlags(&evJoin, cudaEventDisableTiming);

    cudaEventRecord(evFork, 0);
    cudaStreamWaitEvent(s2, evFork, 0);

    // Adjacency build on main stream
    k_zero_cnt<<<(NN + 255) / 256, 256>>>();
    k_bucket<<<(EE + 255) / 256, 256>>>(src, dst);
    // gemm1 on side stream
    k_gemm1<<<(NN + G1_TN - 1) / G1_TN, 256, 0, s2>>>(x, W1l, b1l, W1r, b1r);
    cudaEventRecord(evJoin, s2);
    k_selfslot<<<(NN + 255) / 256, 256>>>();

    // join before layer-1 aggregation
    cudaStreamWaitEvent(0, evJoin, 0);
    k_agg1<<<(NN + 7) / 8, 256>>>(att1, bias1);

    // Layer 2
    k_gemm2<<<(NN + G2_TM - 1) / G2_TM, G2_TM>>>(W2l, b2l, W2r, b2r);
    k_agg2<<<(NN + 7) / 8, 256>>>(att2, bias2, (float*)d_out);
}

// round 17
// speedup vs baseline: 1.0425x; 1.0425x over previous
#include <cuda_runtime.h>
#include <math_constants.h>

#define NN   100000
#define EE   800000
#define FIN  14
#define HC   128      // H1*C1
#define H1   4
#define C1   32
#define C2   21
#define SLOPE 0.2f

// ---- scratch (device globals; no allocation allowed) ----
__device__ __align__(16) float g_xl1[NN * HC];
__device__ __align__(16) float g_xr1[NN * HC];
__device__ __align__(16) float g_h  [NN * HC];
__device__ float g_hl2[NN * C2 + 32];
__device__ float g_hr2[NN * C2 + 32];
__device__ int   g_cnt[NN];
__device__ int   g_rowptr[NN];
__device__ int   g_cursor[NN];
__device__ int   g_csr_src[EE];
__device__ int   g_bsum[128];

// ---------------- CSR build ----------------
__global__ void k_zero_cnt() {
    int i = blockIdx.x * blockDim.x + threadIdx.x;
    if (i < NN) g_cnt[i] = 0;
}

__global__ void k_count(const int* __restrict__ dst) {
    int e = blockIdx.x * blockDim.x + threadIdx.x;
    if (e < EE) atomicAdd(&g_cnt[dst[e]], 1);
}

__global__ void k_scan1() {
    __shared__ int s[1024];
    int i = blockIdx.x * 1024 + threadIdx.x;
    int v = (i < NN) ? g_cnt[i] : 0;
    s[threadIdx.x] = v;
    __syncthreads();
    for (int off = 1; off < 1024; off <<= 1) {
        int t = (threadIdx.x >= off) ? s[threadIdx.x - off] : 0;
        __syncthreads();
        s[threadIdx.x] += t;
        __syncthreads();
    }
    if (i < NN) g_rowptr[i] = s[threadIdx.x] - v;   // exclusive scan
    if (threadIdx.x == 1023) g_bsum[blockIdx.x] = s[1023];
}

// parallel scan of <=128 block sums (one block, 128 threads)
__global__ void k_scan2(int nb) {
    int t = threadIdx.x;
    int lane = t & 31, w = t >> 5;
    int v = (t < nb) ? g_bsum[t] : 0;
    int x = v;
#pragma unroll
    for (int off = 1; off < 32; off <<= 1) {
        int y = __shfl_up_sync(0xffffffffu, x, off);
        if (lane >= off) x += y;
    }
    __shared__ int ws[4];
    if (lane == 31) ws[w] = x;
    __syncthreads();
    if (t < 4) {
        int s = ws[t];
        int y0 = __shfl_up_sync(0xfu, s, 1); if (t >= 1) s += y0;
        int y1 = __shfl_up_sync(0xfu, s, 2); if (t >= 2) s += y1;
        ws[t] = s;
    }
    __syncthreads();
    int base = (w > 0) ? ws[w - 1] : 0;
    if (t < nb) g_bsum[t] = base + x - v;   // exclusive
}

__global__ void k_scan3() {
    int i = blockIdx.x * blockDim.x + threadIdx.x;
    if (i < NN) {
        int v = g_rowptr[i] + g_bsum[i >> 10];
        g_rowptr[i] = v;
        g_cursor[i] = v;
    }
}

__global__ void k_fill(const int* __restrict__ src, const int* __restrict__ dst) {
    int e = blockIdx.x * blockDim.x + threadIdx.x;
    if (e < EE) {
        int d = dst[e];
        int pos = atomicAdd(&g_cursor[d], 1);
        g_csr_src[pos] = src[e];
    }
}

// ---------------- Layer 1 GEMM: 256 threads, 256-node tile, 2 cols/thread ----------------
#define G1_TN 256
#define G1_STRIDE 260
__global__ void k_gemm1(const float* __restrict__ x,
                        const float* __restrict__ Wl, const float* __restrict__ bl,
                        const float* __restrict__ Wr, const float* __restrict__ br) {
    __shared__ float sxT[FIN * G1_STRIDE];
    int t = threadIdx.x;              // 256 threads
    int base = blockIdx.x * G1_TN;
    int nh   = t >> 7;                // node half
    int half = (t & 127) >> 6;        // 0 = l, 1 = r
    int c2   = (t & 63) * 2;
    const float* W = half ? Wr : Wl;
    const float* B = half ? br : bl;
    float w0[FIN], w1[FIN];
#pragma unroll
    for (int k = 0; k < FIN; k++) {
        w0[k] = __ldg(&W[k * HC + c2]);
        w1[k] = __ldg(&W[k * HC + c2 + 1]);
    }
    float b0 = __ldg(&B[c2]), b1 = __ldg(&B[c2 + 1]);

    for (int idx = t; idx < G1_TN * FIN; idx += 256) {
        int n = idx / FIN, k = idx - n * FIN;
        float v = (base + n < NN) ? x[(base + n) * FIN + k] : 0.f;
        sxT[k * G1_STRIDE + n] = v;
    }
    __syncthreads();

    float* outp = half ? g_xr1 : g_xl1;
    int noff = nh * 128;
#pragma unroll 2
    for (int n0 = 0; n0 < 128; n0 += 4) {
        float a00 = b0, a01 = b0, a02 = b0, a03 = b0;
        float a10 = b1, a11 = b1, a12 = b1, a13 = b1;
#pragma unroll
        for (int k = 0; k < FIN; k++) {
            float4 xv = *(const float4*)&sxT[k * G1_STRIDE + noff + n0];
            a00 += xv.x * w0[k]; a10 += xv.x * w1[k];
            a01 += xv.y * w0[k]; a11 += xv.y * w1[k];
            a02 += xv.z * w0[k]; a12 += xv.z * w1[k];
            a03 += xv.w * w0[k]; a13 += xv.w * w1[k];
        }
        int n = base + noff + n0;
        if (n + 3 < NN) {
            *(float2*)&outp[(n + 0) * HC + c2] = make_float2(a00, a10);
            *(float2*)&outp[(n + 1) * HC + c2] = make_float2(a01, a11);
            *(float2*)&outp[(n + 2) * HC + c2] = make_float2(a02, a12);
            *(float2*)&outp[(n + 3) * HC + c2] = make_float2(a03, a13);
        } else {
            if (n + 0 < NN) *(float2*)&outp[(n + 0) * HC + c2] = make_float2(a00, a10);
            if (n + 1 < NN) *(float2*)&outp[(n + 1) * HC + c2] = make_float2(a01, a11);
            if (n + 2 < NN) *(float2*)&outp[(n + 2) * HC + c2] = make_float2(a02, a12);
            if (n + 3 < NN) *(float2*)&outp[(n + 3) * HC + c2] = make_float2(a03, a13);
        }
    }
}

// ---------------- Layer 1 aggregation: champion loop + occupancy cap ----------------
// occ was 41% (reg-limited, 52 regs). __launch_bounds__(256,5) caps regs at ~51
// guaranteeing 5 blocks/SM = 40 warps = 62% occ for this issue-bound kernel.
__global__ void __launch_bounds__(256, 5)
k_agg1(const float* __restrict__ att1, const float* __restrict__ bias1) {
    int tid = threadIdx.x, wid = tid >> 5, lane = tid & 31;
    int node = blockIdx.x * 8 + wid;
    if (node >= NN) return;
    int c0 = lane * 4;
    float4 xr4 = *(const float4*)&g_xr1[node * HC + c0];
    float att[4];
#pragma unroll
    for (int j = 0; j < 4; j++) att[j] = att1[(lane >> 3) * C1 + (c0 & 31) + j];
    int start = g_rowptr[node];
    int cnt   = g_cnt[node];
    int total = cnt + 1;                         // + implicit self loop

    // srcof(i) is valid for ANY i: beyond cnt it returns node (self-loop row,
    // L1-hot) so prefetches need no guards.
    auto srcof = [&](int i) -> int {
        return (i < cnt) ? __ldg(&g_csr_src[start + i]) : node;
    };
    auto rowof = [&](int i) -> float4 {
        return *(const float4*)&g_xl1[srcof(i) * HC + c0];
    };
    auto score = [&](const float4& v) -> float {
        float a0 = v.x + xr4.x; a0 = a0 > 0.f ? a0 : SLOPE * a0;
        float a1 = v.y + xr4.y; a1 = a1 > 0.f ? a1 : SLOPE * a1;
        float a2 = v.z + xr4.z; a2 = a2 > 0.f ? a2 : SLOPE * a2;
        float a3 = v.w + xr4.w; a3 = a3 > 0.f ? a3 : SLOPE * a3;
        float p = a0 * att[0] + a1 * att[1] + a2 * att[2] + a3 * att[3];
        p += __shfl_xor_sync(0xffffffffu, p, 1);
        p += __shfl_xor_sync(0xffffffffu, p, 2);
        p += __shfl_xor_sync(0xffffffffu, p, 4);
        return p;
    };

    float dsum0 = 0.f, dsum1 = 0.f;
    float4 acc0 = make_float4(0.f, 0.f, 0.f, 0.f);
    float4 acc1 = make_float4(0.f, 0.f, 0.f, 0.f);

    float4 vA = rowof(0);
    float4 vB = rowof(1);
    int e = 0;
    for (; e + 1 < total; e += 2) {
        float4 vA2 = rowof(e + 2);               // unconditional prefetch (dummy = self row)
        float4 vB2 = rowof(e + 3);
        float pA = score(vA);                    // two independent shuffle chains
        float pB = score(vB);
        float wA = __expf(pA);
        float wB = __expf(pB);
        dsum0 += wA;
        acc0.x += wA * vA.x; acc0.y += wA * vA.y; acc0.z += wA * vA.z; acc0.w += wA * vA.w;
        dsum1 += wB;
        acc1.x += wB * vB.x; acc1.y += wB * vB.y; acc1.z += wB * vB.z; acc1.w += wB * vB.w;
        vA = vA2; vB = vB2;
    }
    if (e < total) {                             // odd tail
        float pA = score(vA);
        float wA = __expf(pA);
        dsum0 += wA;
        acc0.x += wA * vA.x; acc0.y += wA * vA.y; acc0.z += wA * vA.z; acc0.w += wA * vA.w;
    }
    float inv = 1.f / (dsum0 + dsum1);
    float o0 = (acc0.x + acc1.x) * inv + bias1[c0];
    float o1 = (acc0.y + acc1.y) * inv + bias1[c0 + 1];
    float o2 = (acc0.z + acc1.z) * inv + bias1[c0 + 2];
    float o3 = (acc0.w + acc1.w) * inv + bias1[c0 + 3];
    o0 = o0 > 0.f ? o0 : (__expf(o0) - 1.f);     // ELU
    o1 = o1 > 0.f ? o1 : (__expf(o1) - 1.f);
    o2 = o2 > 0.f ? o2 : (__expf(o2) - 1.f);
    o3 = o3 > 0.f ? o3 : (__expf(o3) - 1.f);
    *(float4*)&g_h[node * HC + c0] = make_float4(o0, o1, o2, o3);
}

// ---------------- Layer 2 GEMM: 128-node tile, 128 threads ----------------
#define G2_TM 128
__global__ void k_gemm2(const float* __restrict__ Wl, const float* __restrict__ bl,
                        const float* __restrict__ Wr, const float* __restrict__ br) {
    __shared__ float sh[64][G2_TM + 1];
    __shared__ float sw[64][48];
    int tid = threadIdx.x;                // 128 threads
    int base = blockIdx.x * G2_TM;
    int node = base + tid;
    float acc[44];
#pragma unroll
    for (int j = 0; j < 44; j++) acc[j] = 0.f;

    for (int half = 0; half < 2; half++) {
        int k0 = half * 64;
        for (int idx = tid; idx < 64 * 21; idx += 128) {
            int kk = idx / 21, j = idx % 21;
            sw[kk][j]      = Wl[(k0 + kk) * C2 + j];
            sw[kk][21 + j] = Wr[(k0 + kk) * C2 + j];
        }
        for (int idx = tid; idx < 64; idx += 128) {
#pragma unroll
            for (int j = 42; j < 48; j++) sw[idx][j] = 0.f;
        }
        for (int idx = tid; idx < 32 * G2_TM; idx += 128) {
            int m = idx >> 5, kp = idx & 31;
            float2 hv = make_float2(0.f, 0.f);
            if (base + m < NN) hv = *(const float2*)&g_h[(base + m) * HC + k0 + kp * 2];
            sh[kp * 2 + 0][m] = hv.x;
            sh[kp * 2 + 1][m] = hv.y;
        }
        __syncthreads();
#pragma unroll 4
        for (int k = 0; k < 64; k++) {
            float hk = sh[k][tid];
#pragma unroll
            for (int j4 = 0; j4 < 44; j4 += 4) {
                float4 w4 = *(const float4*)&sw[k][j4];
                acc[j4]     += hk * w4.x;
                acc[j4 + 1] += hk * w4.y;
                acc[j4 + 2] += hk * w4.z;
                acc[j4 + 3] += hk * w4.w;
            }
        }
        __syncthreads();
    }
    if (node < NN) {
#pragma unroll
        for (int j = 0; j < C2; j++) g_hl2[node * C2 + j] = acc[j] + bl[j];
#pragma unroll
        for (int j = 0; j < C2; j++) g_hr2[node * C2 + j] = acc[21 + j] + br[j];
    }
}

// ---------------- Layer 2 aggregation: champion loop + occupancy cap ----------------
__global__ void __launch_bounds__(256, 5)
k_agg2(const float* __restrict__ att2, const float* __restrict__ bias2,
       float* __restrict__ out) {
    int tid = threadIdx.x, wid = tid >> 5, lane = tid & 31;
    int node = blockIdx.x * 8 + wid;
    if (node >= NN) return;
    bool act = lane < C2;
    float xr = act ? g_hr2[node * C2 + lane] : 0.f;
    float av = act ? att2[lane] : 0.f;
    int start = g_rowptr[node];
    int cnt   = g_cnt[node];
    int total = cnt + 1;

    auto srcof = [&](int i) -> int {
        return (i < cnt) ? __ldg(&g_csr_src[start + i]) : node;
    };
    auto loadx = [&](int i) -> float {
        return act ? __ldg(&g_hl2[srcof(i) * C2 + lane]) : 0.f;
    };
    auto score = [&](float xs) -> float {
        float vv = xs + xr;
        vv = vv > 0.f ? vv : SLOPE * vv;
        float p = vv * av;                        // inactive lanes contribute 0
#pragma unroll
        for (int off = 16; off; off >>= 1) p += __shfl_xor_sync(0xffffffffu, p, off);
        return p;
    };

    float dsum0 = 0.f, dsum1 = 0.f, acc0 = 0.f, acc1 = 0.f;
    float xA = loadx(0);
    float xB = loadx(1);
    int e = 0;
    for (; e + 1 < total; e += 2) {
        float xA2 = loadx(e + 2);
        float xB2 = loadx(e + 3);
        float pA = score(xA);
        float pB = score(xB);
        float wA = __expf(pA);
        float wB = __expf(pB);
        dsum0 += wA; acc0 += wA * xA;
        dsum1 += wB; acc1 += wB * xB;
        xA = xA2; xB = xB2;
    }
    if (e < total) {
        float pA = score(xA);
        float wA = __expf(pA);
        dsum0 += wA; acc0 += wA * xA;
    }
    if (act) out[node * C2 + lane] = (acc0 + acc1) / (dsum0 + dsum1) + bias2[lane];
}

// ---------------- launch ----------------
extern "C" void kernel_launch(void* const* d_in, const int* in_sizes, int n_in,
                              void* d_out, int out_size) {
    const float* x     = (const float*)d_in[0];
    const int*   ei    = (const int*)  d_in[1];
    const float* W1l   = (const float*)d_in[2];
    const float* b1l   = (const float*)d_in[3];
    const float* W1r   = (const float*)d_in[4];
    const float* b1r   = (const float*)d_in[5];
    const float* att1  = (const float*)d_in[6];
    const float* bias1 = (const float*)d_in[7];
    const float* W2l   = (const float*)d_in[8];
    const float* b2l   = (const float*)d_in[9];
    const float* W2r   = (const float*)d_in[10];
    const float* b2r   = (const float*)d_in[11];
    const float* att2  = (const float*)d_in[12];
    const float* bias2 = (const float*)d_in[13];
    const int* src = ei;         // edge_index[0]
    const int* dst = ei + EE;    // edge_index[1]

    // Fork: gemm1 runs concurrently with the CSR build branch.
    cudaStream_t s2;
    cudaEvent_t evFork, evJoin;
    cudaStreamCreateWithFlags(&s2, cudaStreamNonBlocking);
    cudaEventCreateWithFlags(&evFork, cudaEventDisableTiming);
    cudaEventCreateWithFlags(&evJoin, cudaEventDisableTiming);

    cudaEventRecord(evFork, 0);
    cudaStreamWaitEvent(s2, evFork, 0);

    // CSR build on the main (capturing) stream
    k_zero_cnt<<<(NN + 255) / 256, 256>>>();
    k_count<<<(EE + 255) / 256, 256>>>(dst);
    k_scan1<<<(NN + 1023) / 1024, 1024>>>();
    // gemm1 on side stream — 4th launch = ncu profiled slot
    k_gemm1<<<(NN + G1_TN - 1) / G1_TN, 256, 0, s2>>>(x, W1l, b1l, W1r, b1r);
    cudaEventRecord(evJoin, s2);
    k_scan2<<<1, 128>>>((NN + 1023) / 1024);
    k_scan3<<<(NN + 255) / 256, 256>>>();
    k_fill<<<(EE + 255) / 256, 256>>>(src, dst);

    // join before layer-1 aggregation
    cudaStreamWaitEvent(0, evJoin, 0);
    k_agg1<<<(NN + 7) / 8, 256>>>(att1, bias1);

    // Layer 2
    k_gemm2<<<(NN + G2_TM - 1) / G2_TM, G2_TM>>>(W2l, b2l, W2r, b2r);
    k_agg2<<<(NN + 7) / 8, 256>>>(att2, bias2, (float*)d_out);
}